// round 14
// baseline (speedup 1.0000x reference)
#include <cuda_runtime.h>
#include <cuda_fp16.h>
#include <cstdint>

#define BB 32
#define LL 512
#define DIN 768
#define HH 16
#define DHH 48
#define DOUTC 768
#define M_TOT (BB*LL)
#define NEGC 1e12f
#define SCALEC 0.14433756729740643f     /* 1/sqrt(48) */
#define C2E 0.20823031078486745f        /* SCALEC * log2(e) */
#define NEG2 1.4426950408889634e12f     /* NEGC * log2(e) */

// fp16 scratch (static device globals)
__device__ __half g_x16[3][(size_t)M_TOT * DIN];
__device__ __half g_w16[3][(size_t)DIN * DOUTC];
__device__ __half g_p16[3][(size_t)M_TOT * DOUTC];
__device__ float  g_lg[(size_t)BB * HH * LL];     // -log2(l) per (b,h,q)

__device__ __forceinline__ unsigned packh(float lo, float hi) {
    __half2 h = __floats2half2_rn(lo, hi);
    return *(unsigned*)&h;
}
__device__ __forceinline__ float fex2(float x) {
    float r;
    asm("ex2.approx.f32 %0, %1;" : "=f"(r) : "f"(x));
    return r;
}

__device__ __forceinline__ void mma_f16(float* c, const unsigned* a, const unsigned* b) {
    asm volatile(
        "mma.sync.aligned.m16n8k16.row.col.f32.f16.f16.f32 "
        "{%0,%1,%2,%3}, {%4,%5,%6,%7}, {%8,%9}, {%0,%1,%2,%3};"
        : "+f"(c[0]), "+f"(c[1]), "+f"(c[2]), "+f"(c[3])
        : "r"(a[0]), "r"(a[1]), "r"(a[2]), "r"(a[3]), "r"(b[0]), "r"(b[1]));
}

__device__ __forceinline__ void ldsm4(unsigned* r, uint32_t a) {
    asm volatile("ldmatrix.sync.aligned.m8n8.x4.shared.b16 {%0,%1,%2,%3}, [%4];"
        : "=r"(r[0]), "=r"(r[1]), "=r"(r[2]), "=r"(r[3]) : "r"(a));
}
__device__ __forceinline__ void ldsm4t(unsigned* r, uint32_t a) {
    asm volatile("ldmatrix.sync.aligned.m8n8.x4.trans.shared.b16 {%0,%1,%2,%3}, [%4];"
        : "=r"(r[0]), "=r"(r[1]), "=r"(r[2]), "=r"(r[3]) : "r"(a));
}

__device__ __forceinline__ uint32_t smem_u32(const void* p) {
    uint32_t a;
    asm("{ .reg .u64 t; cvta.to.shared.u64 t, %1; cvt.u32.u64 %0, t; }"
        : "=r"(a) : "l"(p));
    return a;
}

__device__ __forceinline__ void cp16(uint32_t dst, const void* src) {
    asm volatile("cp.async.ca.shared.global [%0], [%1], 16;"
                 :: "r"(dst), "l"(src) : "memory");
}
__device__ __forceinline__ void cp_commit() {
    asm volatile("cp.async.commit_group;" ::: "memory");
}
__device__ __forceinline__ void cp_wait0() {
    asm volatile("cp.async.wait_group 0;" ::: "memory");
}

// ---------------------------------------------------------------------------
// Prep: f32 -> f16 flat convert
// ---------------------------------------------------------------------------
__global__ void conv_f2h(const float* __restrict__ s0, const float* __restrict__ s1,
                         const float* __restrict__ s2, __half* __restrict__ dBase,
                         size_t dStride, int n4) {
    const float* s = (blockIdx.y == 0) ? s0 : (blockIdx.y == 1) ? s1 : s2;
    __half* d = dBase + blockIdx.y * dStride;
    for (int i = blockIdx.x * blockDim.x + threadIdx.x; i < n4;
         i += gridDim.x * blockDim.x) {
        float4 v = ((const float4*)s)[i];
        uint2 o = make_uint2(packh(v.x, v.y), packh(v.z, v.w));
        ((uint2*)d)[i] = o;
    }
}

// ---------------------------------------------------------------------------
// Kernel 1: FP16 proj GEMM, ldmatrix + cp.async (validated R12).
// ---------------------------------------------------------------------------
#define PA 40
#define PB 136
#define NCHUNK (DIN / 32)
__global__ __launch_bounds__(256, 2) void proj16(
    const __half* __restrict__ Xall, const __half* __restrict__ Wall,
    __half* __restrict__ Yall) {
    const __half* X = Xall + (size_t)blockIdx.z * M_TOT * DIN;
    const __half* W = Wall + (size_t)blockIdx.z * DIN * DOUTC;
    __half* Y       = Yall + (size_t)blockIdx.z * M_TOT * DOUTC;

    __shared__ __align__(16) __half As[2][128 * PA];
    __shared__ __align__(16) __half Bs[2][32 * PB];

    const int t = threadIdx.x, lane = t & 31, w = t >> 5;
    const int g = lane >> 2, tig = lane & 3;
    const int m0 = (w >> 2) * 64, n0 = (w & 3) * 32;
    const int mBase = blockIdx.y * 128, nBase = blockIdx.x * 128;

    const int arow = t >> 1, ah = t & 1;
    const int brow = t >> 3, bn = (t & 7) * 16;
    const __half* Xp = X + (size_t)(mBase + arow) * DIN + ah * 16;
    const __half* Wp = W + (size_t)brow * DOUTC + nBase + bn;

    const uint32_t aBase = smem_u32(As);
    const uint32_t bBase = smem_u32(Bs);
    const uint32_t aDst = aBase + (uint32_t)(arow * PA + ah * 16) * 2;
    const uint32_t bDst = bBase + (uint32_t)(brow * PB + bn) * 2;
    const int aLO = (lane & 15) * PA + (lane >> 4) * 8;
    const int bLO = ((lane & 7) + ((lane >> 3) & 1) * 8) * PB + (lane >> 4) * 8;

    float acc[4][4][4];
    #pragma unroll
    for (int i = 0; i < 4; i++)
        #pragma unroll
        for (int j = 0; j < 4; j++)
            #pragma unroll
            for (int c = 0; c < 4; c++) acc[i][j][c] = 0.0f;

    cp16(aDst, Xp);
    cp16(aDst + 16, Xp + 8);
    cp16(bDst, Wp);
    cp16(bDst + 16, Wp + 8);
    cp_commit();
    cp_wait0();
    __syncthreads();

    for (int c = 0; c < NCHUNK; c++) {
        const int cur = c & 1;
        const bool more = (c + 1 < NCHUNK);
        if (more) {
            const int kk = (c + 1) * 32;
            const int nxt = cur ^ 1;
            const uint32_t aD2 = aBase + (uint32_t)(nxt * 128 * PA + arow * PA + ah * 16) * 2;
            const uint32_t bD2 = bBase + (uint32_t)(nxt * 32 * PB + brow * PB + bn) * 2;
            cp16(aD2, Xp + kk);
            cp16(aD2 + 16, Xp + kk + 8);
            cp16(bD2, Wp + (size_t)kk * DOUTC);
            cp16(bD2 + 16, Wp + (size_t)kk * DOUTC + 8);
            cp_commit();
        }

        const uint32_t aB = aBase + cur * (128 * PA * 2);
        const uint32_t bB = bBase + cur * (32 * PB * 2);
        #pragma unroll
        for (int ks = 0; ks < 2; ks++) {
            const int k0 = ks * 16;
            unsigned a[4][4];
            #pragma unroll
            for (int i = 0; i < 4; i++)
                ldsm4(a[i], aB + (uint32_t)(((m0 + i * 16) * PA) + k0 + aLO) * 2);
            #pragma unroll
            for (int jp = 0; jp < 2; jp++) {
                unsigned b4[4];
                ldsm4t(b4, bB + (uint32_t)((k0 * PB) + n0 + jp * 16 + bLO) * 2);
                #pragma unroll
                for (int i = 0; i < 4; i++) {
                    mma_f16(acc[i][jp * 2 + 0], a[i], b4);
                    mma_f16(acc[i][jp * 2 + 1], a[i], b4 + 2);
                }
            }
        }

        if (more) cp_wait0();
        __syncthreads();
    }

    #pragma unroll
    for (int i = 0; i < 4; i++) {
        const size_t r1 = (size_t)(mBase + m0 + i * 16 + g);
        const size_t r2 = r1 + 8;
        #pragma unroll
        for (int j = 0; j < 4; j++) {
            const int col = nBase + n0 + j * 8 + tig * 2;
            *(__half2*)(Y + r1 * DOUTC + col) = __floats2half2_rn(acc[i][j][0], acc[i][j][1]);
            *(__half2*)(Y + r2 * DOUTC + col) = __floats2half2_rn(acc[i][j][2], acc[i][j][3]);
        }
    }
}

// ---------------------------------------------------------------------------
// Kernel 2a: attn_sums — S + exp + column sums -> g_lg = -log2(l).
// 512 threads per (b,h); balanced dual-tile k-ownership.
// ---------------------------------------------------------------------------
#define RP 56
#define SA_OFF_QS   57344
#define SA_OFF_SSUM 64512
#define SMEM_SUMS   68608

__global__ __launch_bounds__(512, 1) void attn_sums(
    const __half* __restrict__ P16, const int* __restrict__ Vlen,
    float* __restrict__ lg) {
    extern __shared__ char smem[];
    __half* KrH = (__half*)smem;
    __half* QsH = (__half*)(smem + SA_OFF_QS);
    float*  sSum = (float*)(smem + SA_OFF_SSUM);   // [16][64]
    const uint32_t krB = smem_u32(smem);
    const uint32_t qsB = krB + SA_OFF_QS;

    const int bh = blockIdx.x;
    const int b = bh >> 4, h = bh & 15;
    const int t = threadIdx.x, lane = t & 31, w = t >> 5;
    const int g = lane >> 2, tig = lane & 3;
    const int rowA = w * 16, rowB = 496 - w * 16;
    const int vlen = Vlen[b];
    const float bias2 = (vlen == 0) ? NEG2 : 0.0f;

    const int aSel = (lane & 15) * RP + (lane >> 4) * 8;
    const int bSel = ((lane & 7) + ((lane >> 4) << 3)) * RP + ((lane >> 3) & 1) * 8;

    const __half* qsrc = P16 + (size_t)(b * LL) * DOUTC + h * DHH;
    const __half* ksrc = qsrc + (size_t)M_TOT * DOUTC;

    for (int i = t; i < 3072; i += 512) {
        const int row = i / 6, c4 = i % 6;
        *(uint4*)(KrH + row * RP + c4 * 8) =
            *(const uint4*)(ksrc + (size_t)row * DOUTC + c4 * 8);
    }

    const int row0 = t / 6, c40 = t % 6;       // t<384 stages Q
    const __half* src0 = qsrc + (size_t)row0 * DOUTC + c40 * 8;
    __half* dst0 = QsH + row0 * RP + c40 * 8;

    for (int qt = 0; qt < 8; qt++) {
        uint4 p0;
        if (t < 384) p0 = *(const uint4*)(src0 + (size_t)(qt * 64) * DOUTC);
        __syncthreads();
        if (t < 384) *(uint4*)dst0 = p0;
        __syncthreads();

        #pragma unroll
        for (int sub = 0; sub < 2; sub++) {
            const int qc = sub * 32;
            const int qbase = qt * 64 + qc;
            const bool liveA = (rowA <= qbase + 31);
            const bool liveB = (rowB <= qbase + 31);

            float csum[4][2];
            #pragma unroll
            for (int n = 0; n < 4; n++) { csum[n][0] = 0.0f; csum[n][1] = 0.0f; }

            if (liveA || liveB) {
                float ac[2][4][4];
                #pragma unroll
                for (int mt = 0; mt < 2; mt++)
                    #pragma unroll
                    for (int n = 0; n < 4; n++)
                        #pragma unroll
                        for (int c = 0; c < 4; c++) ac[mt][n][c] = 0.0f;
                #pragma unroll
                for (int jd = 0; jd < 3; jd++) {
                    unsigned bq[2][4];
                    ldsm4(bq[0], qsB + (uint32_t)(qc * RP + jd * 16 + bSel) * 2);
                    ldsm4(bq[1], qsB + (uint32_t)((qc + 16) * RP + jd * 16 + bSel) * 2);
                    if (liveA) {
                        unsigned a0[4];
                        ldsm4(a0, krB + (uint32_t)(rowA * RP + jd * 16 + aSel) * 2);
                        mma_f16(ac[0][0], a0, bq[0]);
                        mma_f16(ac[0][1], a0, bq[0] + 2);
                        mma_f16(ac[0][2], a0, bq[1]);
                        mma_f16(ac[0][3], a0, bq[1] + 2);
                    }
                    if (liveB) {
                        unsigned a1[4];
                        ldsm4(a1, krB + (uint32_t)(rowB * RP + jd * 16 + aSel) * 2);
                        mma_f16(ac[1][0], a1, bq[0]);
                        mma_f16(ac[1][1], a1, bq[0] + 2);
                        mma_f16(ac[1][2], a1, bq[1]);
                        mma_f16(ac[1][3], a1, bq[1] + 2);
                    }
                }
                #pragma unroll
                for (int mt = 0; mt < 2; mt++) {
                    if (mt == 0 ? !liveA : !liveB) continue;
                    const int rowX = (mt == 0) ? rowA : rowB;
                    const int kg0 = rowX + g, kg1 = kg0 + 8;
                    const bool nomask = (rowX + 15 <= qbase) && (rowX + 15 < vlen);
                    if (nomask) {
                        #pragma unroll
                        for (int n = 0; n < 4; n++) {
                            csum[n][0] += fex2(ac[mt][n][0] * C2E) + fex2(ac[mt][n][2] * C2E);
                            csum[n][1] += fex2(ac[mt][n][1] * C2E) + fex2(ac[mt][n][3] * C2E);
                        }
                    } else {
                        const float v0 = (kg0 >= vlen) ? NEG2 : 0.0f;
                        const float v1 = (kg1 >= vlen) ? NEG2 : 0.0f;
                        #pragma unroll
                        for (int n = 0; n < 4; n++) {
                            const int q0 = qbase + n * 8 + tig * 2;
                            float s0 = ac[mt][n][0] * C2E - v0;
                            float s1 = ac[mt][n][1] * C2E - v0;
                            float s2 = ac[mt][n][2] * C2E - v1;
                            float s3 = ac[mt][n][3] * C2E - v1;
                            if (kg0 > q0)     s0 -= NEG2;
                            if (kg0 > q0 + 1) s1 -= NEG2;
                            if (kg1 > q0)     s2 -= NEG2;
                            if (kg1 > q0 + 1) s3 -= NEG2;
                            csum[n][0] += fex2(s0 + bias2) + fex2(s2 + bias2);
                            csum[n][1] += fex2(s1 + bias2) + fex2(s3 + bias2);
                        }
                    }
                }
            }
            #pragma unroll
            for (int n = 0; n < 4; n++)
                #pragma unroll
                for (int p = 0; p < 2; p++) {
                    float v = csum[n][p];
                    v += __shfl_xor_sync(0xffffffffu, v, 4);
                    v += __shfl_xor_sync(0xffffffffu, v, 8);
                    v += __shfl_xor_sync(0xffffffffu, v, 16);
                    csum[n][p] = v;
                }
            if (g == 0) {
                #pragma unroll
                for (int n = 0; n < 4; n++)
                    *(float2*)&sSum[w * 64 + sub * 32 + n * 8 + tig * 2] =
                        make_float2(csum[n][0], csum[n][1]);
            }
        }
        __syncthreads();
        if (t < 64) {
            float l = 0.0f;
            #pragma unroll
            for (int w2 = 0; w2 < 16; w2++) l += sSum[w2 * 64 + t];
            lg[(size_t)bh * LL + qt * 64 + t] = -__log2f(l);
        }
    }
}

// ---------------------------------------------------------------------------
// Kernel 2b: attn_o — O = exp(S+lg)^T · V, no softmax barriers.
// 256 threads, block = (bh, k-half); 8 warps x 2 balanced tiles of 16 rows.
// ---------------------------------------------------------------------------
#define OB_OFF_QS  28672
#define OB_OFF_VS  35840
#define OB_OFF_LG  43008
#define SMEM_OB    43264

__global__ __launch_bounds__(256, 2) void attn_o(
    const __half* __restrict__ P16, const float* __restrict__ lg,
    const int* __restrict__ Qlen, const int* __restrict__ Vlen,
    float* __restrict__ Out) {
    extern __shared__ char smem[];
    __half* KrH = (__half*)smem;               // [256][RP] local k rows
    __half* QsH = (__half*)(smem + OB_OFF_QS);
    __half* VsH = (__half*)(smem + OB_OFF_VS);
    float*  lgS = (float*)(smem + OB_OFF_LG);  // [64]
    const uint32_t krB = smem_u32(smem);
    const uint32_t qsB = krB + OB_OFF_QS;
    const uint32_t vsB = krB + OB_OFF_VS;

    const int bh = blockIdx.x >> 1;
    const int khalf = blockIdx.x & 1;
    const int base = khalf * 256;
    const int b = bh >> 4, h = bh & 15;
    const int t = threadIdx.x, lane = t & 31, w = t >> 5;
    const int g = lane >> 2, tig = lane & 3;
    const int rowAL = w * 16, rowBL = 240 - w * 16;       // local
    const int rowA = base + rowAL, rowB = base + rowBL;   // global
    const int vlen = Vlen[b], qlen = Qlen[b];
    const float bias2 = (vlen == 0) ? NEG2 : 0.0f;

    const int aSel = (lane & 15) * RP + (lane >> 4) * 8;
    const int bSel = ((lane & 7) + ((lane >> 4) << 3)) * RP + ((lane >> 3) & 1) * 8;
    const int tSel = ((lane & 7) + (((lane >> 3) & 1) << 3)) * RP + (lane >> 4) * 8;

    const __half* qsrc = P16 + (size_t)(b * LL) * DOUTC + h * DHH;
    const __half* ksrc = qsrc + (size_t)M_TOT * DOUTC;
    const __half* vsrc = ksrc + (size_t)M_TOT * DOUTC;
    const float* lgp = lg + (size_t)bh * LL;

    // K resident: 256 local rows (global base+row)
    for (int i = t; i < 1536; i += 256) {
        const int row = i / 6, c4 = i % 6;
        *(uint4*)(KrH + row * RP + c4 * 8) =
            *(const uint4*)(ksrc + (size_t)(base + row) * DOUTC + c4 * 8);
    }

    // staging map: 3 uint4/thread (idx = t + j*256; idx<384 Q else V)
    const __half* ssrc[3];
    __half* sdst[3];
    #pragma unroll
    for (int j = 0; j < 3; j++) {
        const int idx = t + j * 256;
        const int isV = idx >= 384;
        const int k = isV ? idx - 384 : idx;
        const int row = k / 6, c4 = k % 6;
        ssrc[j] = (isV ? vsrc : qsrc) + (size_t)row * DOUTC + c4 * 8;
        sdst[j] = (isV ? VsH : QsH) + row * RP + c4 * 8;
    }

    float oacc[2][6][4];
    #pragma unroll
    for (int mt = 0; mt < 2; mt++)
        #pragma unroll
        for (int nd = 0; nd < 6; nd++)
            #pragma unroll
            for (int c = 0; c < 4; c++) oacc[mt][nd][c] = 0.0f;

    for (int qt = 0; qt < 8; qt++) {
        if (qt * 64 + 63 < base) continue;   // whole chunk causally dead for this half
        const size_t qoff = (size_t)(qt * 64) * DOUTC;
        uint4 pp[3];
        #pragma unroll
        for (int j = 0; j < 3; j++) pp[j] = *(const uint4*)(ssrc[j] + qoff);
        float lgv;
        if (t < 64) lgv = lgp[qt * 64 + t];
        __syncthreads();
        #pragma unroll
        for (int j = 0; j < 3; j++) *(uint4*)sdst[j] = pp[j];
        if (t < 64) lgS[t] = lgv;
        __syncthreads();

        #pragma unroll
        for (int sub = 0; sub < 2; sub++) {
            const int qc = sub * 32;
            const int qbase = qt * 64 + qc;
            const bool liveA = (rowA <= qbase + 31);
            const bool liveB = (rowB <= qbase + 31);
            if (!liveA && !liveB) continue;

            float ac[2][4][4];
            #pragma unroll
            for (int mt = 0; mt < 2; mt++)
                #pragma unroll
                for (int n = 0; n < 4; n++)
                    #pragma unroll
                    for (int c = 0; c < 4; c++) ac[mt][n][c] = 0.0f;
            #pragma unroll
            for (int jd = 0; jd < 3; jd++) {
                unsigned bq[2][4];
                ldsm4(bq[0], qsB + (uint32_t)(qc * RP + jd * 16 + bSel) * 2);
                ldsm4(bq[1], qsB + (uint32_t)((qc + 16) * RP + jd * 16 + bSel) * 2);
                if (liveA) {
                    unsigned a0[4];
                    ldsm4(a0, krB + (uint32_t)(rowAL * RP + jd * 16 + aSel) * 2);
                    mma_f16(ac[0][0], a0, bq[0]);
                    mma_f16(ac[0][1], a0, bq[0] + 2);
                    mma_f16(ac[0][2], a0, bq[1]);
                    mma_f16(ac[0][3], a0, bq[1] + 2);
                }
                if (liveB) {
                    unsigned a1[4];
                    ldsm4(a1, krB + (uint32_t)(rowBL * RP + jd * 16 + aSel) * 2);
                    mma_f16(ac[1][0], a1, bq[0]);
                    mma_f16(ac[1][1], a1, bq[0] + 2);
                    mma_f16(ac[1][2], a1, bq[1]);
                    mma_f16(ac[1][3], a1, bq[1] + 2);
                }
            }

            // exp with folded 1/l (lg) + masks; pack A fragments
            unsigned aa[2][2][4];    // [mt][kc][frag]
            #pragma unroll
            for (int mt = 0; mt < 2; mt++) {
                if (mt == 0 ? !liveA : !liveB) continue;
                const int rowX = (mt == 0) ? rowA : rowB;
                const int kg0 = rowX + g, kg1 = kg0 + 8;
                const bool nomask = (rowX + 15 <= qbase) && (rowX + 15 < vlen);
                const float v0 = nomask ? 0.0f : ((kg0 >= vlen) ? NEG2 : 0.0f);
                const float v1 = nomask ? 0.0f : ((kg1 >= vlen) ? NEG2 : 0.0f);
                #pragma unroll
                for (int n = 0; n < 4; n++) {
                    const int q0 = qbase + n * 8 + tig * 2;
                    const float2 lg01 = *(const float2*)&lgS[qc + n * 8 + tig * 2];
                    float s0 = ac[mt][n][0] * C2E + lg01.x - v0;
                    float s1 = ac[mt][n][1] * C2E + lg01.y - v0;
                    float s2 = ac[mt][n][2] * C2E + lg01.x - v1;
                    float s3 = ac[mt][n][3] * C2E + lg01.y - v1;
                    if (!nomask) {
                        if (kg0 > q0)     s0 -= NEG2;
                        if (kg0 > q0 + 1) s1 -= NEG2;
                        if (kg1 > q0)     s2 -= NEG2;
                        if (kg1 > q0 + 1) s3 -= NEG2;
                    }
                    const float e0 = fex2(s0 + bias2), e1 = fex2(s1 + bias2);
                    const float e2 = fex2(s2 + bias2), e3 = fex2(s3 + bias2);
                    aa[mt][n >> 1][(n & 1) * 2 + 0] = packh(e0, e1);
                    aa[mt][n >> 1][(n & 1) * 2 + 1] = packh(e2, e3);
                }
            }

            #pragma unroll
            for (int kc = 0; kc < 2; kc++) {
                #pragma unroll
                for (int dd = 0; dd < 3; dd++) {
                    unsigned b4[4];
                    ldsm4t(b4, vsB + (uint32_t)((qc + kc * 16) * RP + dd * 16 + tSel) * 2);
                    if (liveA) {
                        mma_f16(oacc[0][dd * 2 + 0], aa[0][kc], b4);
                        mma_f16(oacc[0][dd * 2 + 1], aa[0][kc], b4 + 2);
                    }
                    if (liveB) {
                        mma_f16(oacc[1][dd * 2 + 0], aa[1][kc], b4);
                        mma_f16(oacc[1][dd * 2 + 1], aa[1][kc], b4 + 2);
                    }
                }
            }
        }
    }

    #pragma unroll
    for (int mt = 0; mt < 2; mt++) {
        const int kg0 = (mt == 0 ? rowA : rowB) + g, kg1 = kg0 + 8;
        const float f0 = (kg0 < qlen) ? 1.0f : 0.0f;
        const float f1 = (kg1 < qlen) ? 1.0f : 0.0f;
        #pragma unroll
        for (int nd = 0; nd < 6; nd++) {
            const int col = h * DHH + nd * 8 + tig * 2;
            *(float2*)(Out + (size_t)(b * LL + kg0) * DOUTC + col) =
                make_float2(oacc[mt][nd][0] * f0, oacc[mt][nd][1] * f0);
            *(float2*)(Out + (size_t)(b * LL + kg1) * DOUTC + col) =
                make_float2(oacc[mt][nd][2] * f1, oacc[mt][nd][3] * f1);
        }
    }
}

// ---------------------------------------------------------------------------
extern "C" void kernel_launch(void* const* d_in, const int* in_sizes, int n_in,
                              void* d_out, int out_size) {
    const float* Qseq = (const float*)d_in[0];
    const float* Kseq = (const float*)d_in[1];
    const float* Vseq = (const float*)d_in[2];
    const float* WQ   = (const float*)d_in[3];
    const float* WK   = (const float*)d_in[4];
    const float* WV   = (const float*)d_in[5];
    const int*   Qlen = (const int*)d_in[6];
    const int*   Vlen = (const int*)d_in[7];

    __half *x16, *w16, *p16;
    float* lg;
    cudaGetSymbolAddress((void**)&x16, g_x16);
    cudaGetSymbolAddress((void**)&w16, g_w16);
    cudaGetSymbolAddress((void**)&p16, g_p16);
    cudaGetSymbolAddress((void**)&lg, g_lg);

    cudaFuncSetAttribute(attn_sums, cudaFuncAttributeMaxDynamicSharedMemorySize, SMEM_SUMS);
    cudaFuncSetAttribute(attn_o, cudaFuncAttributeMaxDynamicSharedMemorySize, SMEM_OB);

    conv_f2h<<<dim3(2048, 3), 256>>>(Qseq, Kseq, Vseq, x16,
                                     (size_t)M_TOT * DIN, M_TOT * DIN / 4);
    conv_f2h<<<dim3(576, 3), 256>>>(WQ, WK, WV, w16,
                                    (size_t)DIN * DOUTC, DIN * DOUTC / 4);

    proj16<<<dim3(6, 128, 3), 256>>>(x16, w16, p16);

    attn_sums<<<BB * HH, 512, SMEM_SUMS>>>(p16, Vlen, lg);
    attn_o<<<BB * HH * 2, 256, SMEM_OB>>>(p16, lg, Qlen, Vlen, (float*)d_out);
}

// round 15
// speedup vs baseline: 1.1528x; 1.1528x over previous
#include <cuda_runtime.h>
#include <cuda_fp16.h>
#include <cstdint>

#define BB 32
#define LL 512
#define DIN 768
#define HH 16
#define DHH 48
#define DOUTC 768
#define M_TOT (BB*LL)
#define NEGC 1e12f
#define SCALEC 0.14433756729740643f     /* 1/sqrt(48) */
#define C2E 0.20823031078486745f        /* SCALEC * log2(e) */
#define NEG2 1.4426950408889634e12f     /* NEGC * log2(e) */

// fp16 scratch (static device globals)
__device__ __half g_x16[3][(size_t)M_TOT * DIN];
__device__ __half g_w16[3][(size_t)DIN * DOUTC];
__device__ __half g_p16[3][(size_t)M_TOT * DOUTC];

__device__ __forceinline__ unsigned packh(float lo, float hi) {
    __half2 h = __floats2half2_rn(lo, hi);
    return *(unsigned*)&h;
}
__device__ __forceinline__ unsigned hmul2u(unsigned a, unsigned b) {
    __half2 r = __hmul2(*(__half2*)&a, *(__half2*)&b);
    return *(unsigned*)&r;
}
__device__ __forceinline__ float fex2(float x) {
    float r;
    asm("ex2.approx.f32 %0, %1;" : "=f"(r) : "f"(x));
    return r;
}

__device__ __forceinline__ void mma_f16(float* c, const unsigned* a, const unsigned* b) {
    asm volatile(
        "mma.sync.aligned.m16n8k16.row.col.f32.f16.f16.f32 "
        "{%0,%1,%2,%3}, {%4,%5,%6,%7}, {%8,%9}, {%0,%1,%2,%3};"
        : "+f"(c[0]), "+f"(c[1]), "+f"(c[2]), "+f"(c[3])
        : "r"(a[0]), "r"(a[1]), "r"(a[2]), "r"(a[3]), "r"(b[0]), "r"(b[1]));
}

__device__ __forceinline__ void ldsm4(unsigned* r, uint32_t a) {
    asm volatile("ldmatrix.sync.aligned.m8n8.x4.shared.b16 {%0,%1,%2,%3}, [%4];"
        : "=r"(r[0]), "=r"(r[1]), "=r"(r[2]), "=r"(r[3]) : "r"(a));
}
__device__ __forceinline__ void ldsm4t(unsigned* r, uint32_t a) {
    asm volatile("ldmatrix.sync.aligned.m8n8.x4.trans.shared.b16 {%0,%1,%2,%3}, [%4];"
        : "=r"(r[0]), "=r"(r[1]), "=r"(r[2]), "=r"(r[3]) : "r"(a));
}

__device__ __forceinline__ uint32_t smem_u32(const void* p) {
    uint32_t a;
    asm("{ .reg .u64 t; cvta.to.shared.u64 t, %1; cvt.u32.u64 %0, t; }"
        : "=r"(a) : "l"(p));
    return a;
}

__device__ __forceinline__ void cp16(uint32_t dst, const void* src) {
    asm volatile("cp.async.ca.shared.global [%0], [%1], 16;"
                 :: "r"(dst), "l"(src) : "memory");
}
__device__ __forceinline__ void cp_commit() {
    asm volatile("cp.async.commit_group;" ::: "memory");
}
__device__ __forceinline__ void cp_wait0() {
    asm volatile("cp.async.wait_group 0;" ::: "memory");
}

// ---------------------------------------------------------------------------
// Prep: f32 -> f16, all six tensors in ONE launch (blockIdx.y selects).
// ---------------------------------------------------------------------------
__global__ void conv6(const float* __restrict__ s0, const float* __restrict__ s1,
                      const float* __restrict__ s2, const float* __restrict__ s3,
                      const float* __restrict__ s4, const float* __restrict__ s5) {
    const int y = blockIdx.y;
    const float* s;
    __half* d;
    int n4;
    if (y < 3) {
        s = (y == 0) ? s0 : (y == 1) ? s1 : s2;
        d = g_x16[y];
        n4 = M_TOT * DIN / 4;
    } else {
        s = (y == 3) ? s3 : (y == 4) ? s4 : s5;
        d = g_w16[y - 3];
        n4 = DIN * DOUTC / 4;
    }
    for (int i = blockIdx.x * blockDim.x + threadIdx.x; i < n4;
         i += gridDim.x * blockDim.x) {
        float4 v = ((const float4*)s)[i];
        uint2 o = make_uint2(packh(v.x, v.y), packh(v.z, v.w));
        ((uint2*)d)[i] = o;
    }
}

// ---------------------------------------------------------------------------
// Kernel 1: FP16 proj GEMM, ldmatrix + cp.async (validated R12).
// ---------------------------------------------------------------------------
#define PA 40
#define PB 136
#define NCHUNK (DIN / 32)
__global__ __launch_bounds__(256, 2) void proj16(
    const __half* __restrict__ Xall, const __half* __restrict__ Wall,
    __half* __restrict__ Yall) {
    const __half* X = Xall + (size_t)blockIdx.z * M_TOT * DIN;
    const __half* W = Wall + (size_t)blockIdx.z * DIN * DOUTC;
    __half* Y       = Yall + (size_t)blockIdx.z * M_TOT * DOUTC;

    __shared__ __align__(16) __half As[2][128 * PA];
    __shared__ __align__(16) __half Bs[2][32 * PB];

    const int t = threadIdx.x, lane = t & 31, w = t >> 5;
    const int g = lane >> 2, tig = lane & 3;
    const int m0 = (w >> 2) * 64, n0 = (w & 3) * 32;
    const int mBase = blockIdx.y * 128, nBase = blockIdx.x * 128;

    const int arow = t >> 1, ah = t & 1;
    const int brow = t >> 3, bn = (t & 7) * 16;
    const __half* Xp = X + (size_t)(mBase + arow) * DIN + ah * 16;
    const __half* Wp = W + (size_t)brow * DOUTC + nBase + bn;

    const uint32_t aBase = smem_u32(As);
    const uint32_t bBase = smem_u32(Bs);
    const uint32_t aDst = aBase + (uint32_t)(arow * PA + ah * 16) * 2;
    const uint32_t bDst = bBase + (uint32_t)(brow * PB + bn) * 2;
    const int aLO = (lane & 15) * PA + (lane >> 4) * 8;
    const int bLO = ((lane & 7) + ((lane >> 3) & 1) * 8) * PB + (lane >> 4) * 8;

    float acc[4][4][4];
    #pragma unroll
    for (int i = 0; i < 4; i++)
        #pragma unroll
        for (int j = 0; j < 4; j++)
            #pragma unroll
            for (int c = 0; c < 4; c++) acc[i][j][c] = 0.0f;

    cp16(aDst, Xp);
    cp16(aDst + 16, Xp + 8);
    cp16(bDst, Wp);
    cp16(bDst + 16, Wp + 8);
    cp_commit();
    cp_wait0();
    __syncthreads();

    for (int c = 0; c < NCHUNK; c++) {
        const int cur = c & 1;
        const bool more = (c + 1 < NCHUNK);
        if (more) {
            const int kk = (c + 1) * 32;
            const int nxt = cur ^ 1;
            const uint32_t aD2 = aBase + (uint32_t)(nxt * 128 * PA + arow * PA + ah * 16) * 2;
            const uint32_t bD2 = bBase + (uint32_t)(nxt * 32 * PB + brow * PB + bn) * 2;
            cp16(aD2, Xp + kk);
            cp16(aD2 + 16, Xp + kk + 8);
            cp16(bD2, Wp + (size_t)kk * DOUTC);
            cp16(bD2 + 16, Wp + (size_t)kk * DOUTC + 8);
            cp_commit();
        }

        const uint32_t aB = aBase + cur * (128 * PA * 2);
        const uint32_t bB = bBase + cur * (32 * PB * 2);
        #pragma unroll
        for (int ks = 0; ks < 2; ks++) {
            const int k0 = ks * 16;
            unsigned a[4][4];
            #pragma unroll
            for (int i = 0; i < 4; i++)
                ldsm4(a[i], aB + (uint32_t)(((m0 + i * 16) * PA) + k0 + aLO) * 2);
            #pragma unroll
            for (int jp = 0; jp < 2; jp++) {
                unsigned b4[4];
                ldsm4t(b4, bB + (uint32_t)((k0 * PB) + n0 + jp * 16 + bLO) * 2);
                #pragma unroll
                for (int i = 0; i < 4; i++) {
                    mma_f16(acc[i][jp * 2 + 0], a[i], b4);
                    mma_f16(acc[i][jp * 2 + 1], a[i], b4 + 2);
                }
            }
        }

        if (more) cp_wait0();
        __syncthreads();
    }

    #pragma unroll
    for (int i = 0; i < 4; i++) {
        const size_t r1 = (size_t)(mBase + m0 + i * 16 + g);
        const size_t r2 = r1 + 8;
        #pragma unroll
        for (int j = 0; j < 4; j++) {
            const int col = nBase + n0 + j * 8 + tig * 2;
            *(__half2*)(Y + r1 * DOUTC + col) = __floats2half2_rn(acc[i][j][0], acc[i][j][1]);
            *(__half2*)(Y + r2 * DOUTC + col) = __floats2half2_rn(acc[i][j][2], acc[i][j][3]);
        }
    }
}

// ---------------------------------------------------------------------------
// Kernel 2: fused attention R15: single pass, balanced dual-tile ownership,
// SEQUENTIAL per-mt S processing to cut register pressure (no spills).
// ---------------------------------------------------------------------------
#define RP 56
#define OFF_QS   57344
#define OFF_VS   64512
#define OFF_SSUM 71680
#define OFF_LS   73728
#define SMEM_ATT 73984

__global__ __launch_bounds__(512, 1) void attn_fused(
    const __half* __restrict__ P16,
    const int* __restrict__ Qlen, const int* __restrict__ Vlen,
    float* __restrict__ Out) {
    extern __shared__ char smem[];
    __half* KrH = (__half*)smem;
    __half* QsH = (__half*)(smem + OFF_QS);
    __half* VsH = (__half*)(smem + OFF_VS);
    float*  sSum = (float*)(smem + OFF_SSUM);   // [16 warps][32 q]
    float*  lSc  = (float*)(smem + OFF_LS);     // [32]
    const uint32_t krB = smem_u32(smem);
    const uint32_t qsB = krB + OFF_QS;
    const uint32_t vsB = krB + OFF_VS;

    const int b = blockIdx.x >> 4, h = blockIdx.x & 15;
    const int t = threadIdx.x, lane = t & 31, w = t >> 5;
    const int g = lane >> 2, tig = lane & 3;
    const int rowA = w * 16;
    const int rowB = 496 - w * 16;
    const int vlen = Vlen[b], qlen = Qlen[b];
    const float bias2 = (vlen == 0) ? NEG2 : 0.0f;

    const int aSel = (lane & 15) * RP + (lane >> 4) * 8;
    const int bSel = ((lane & 7) + ((lane >> 4) << 3)) * RP + ((lane >> 3) & 1) * 8;
    const int tSel = ((lane & 7) + (((lane >> 3) & 1) << 3)) * RP + (lane >> 4) * 8;

    const __half* qsrc = P16 + (size_t)(b * LL) * DOUTC + h * DHH;
    const __half* ksrc = qsrc + (size_t)M_TOT * DOUTC;
    const __half* vsrc = ksrc + (size_t)M_TOT * DOUTC;

    for (int i = t; i < 3072; i += 512) {
        const int row = i / 6, c4 = i % 6;
        *(uint4*)(KrH + row * RP + c4 * 8) =
            *(const uint4*)(ksrc + (size_t)row * DOUTC + c4 * 8);
    }

    const int arr0 = t >= 384;
    const int j0 = arr0 ? t - 384 : t;
    const int row0 = j0 / 6, c40 = j0 % 6;
    const __half* src0 = (arr0 ? vsrc : qsrc) + (size_t)row0 * DOUTC + c40 * 8;
    __half* dst0 = (arr0 ? VsH : QsH) + row0 * RP + c40 * 8;
    const int j1 = t + 128;
    const int row1 = j1 / 6, c41 = j1 % 6;
    const __half* src1 = vsrc + (size_t)row1 * DOUTC + c41 * 8;
    __half* dst1 = VsH + row1 * RP + c41 * 8;

    float oacc[2][6][4];
    #pragma unroll
    for (int mt = 0; mt < 2; mt++)
        #pragma unroll
        for (int nd = 0; nd < 6; nd++)
            #pragma unroll
            for (int c = 0; c < 4; c++) oacc[mt][nd][c] = 0.0f;

    for (int qt = 0; qt < 8; qt++) {
        const size_t qoff = (size_t)(qt * 64) * DOUTC;
        uint4 p0 = *(const uint4*)(src0 + qoff);
        uint4 p1;
        if (t < 256) p1 = *(const uint4*)(src1 + qoff);
        __syncthreads();
        *(uint4*)dst0 = p0;
        if (t < 256) *(uint4*)dst1 = p1;
        __syncthreads();

        #pragma unroll
        for (int sub = 0; sub < 2; sub++) {
            const int qc = sub * 32;
            const int qbase = qt * 64 + qc;
            const bool liveA = (rowA <= qbase + 31);
            const bool liveB = (rowB <= qbase + 31);

            float csum[4][2];
            #pragma unroll
            for (int n = 0; n < 4; n++) { csum[n][0] = 0.0f; csum[n][1] = 0.0f; }

            unsigned aaP[2][2][4];   // [mt][kc][frag] packed exp (unscaled)

            // ---- sequential per-mt S + exp + pack (low register peak) ----
            #pragma unroll
            for (int mt = 0; mt < 2; mt++) {
                const bool liveX = (mt == 0) ? liveA : liveB;
                if (!liveX) continue;
                const int rowX = (mt == 0) ? rowA : rowB;

                float ac[4][4];
                #pragma unroll
                for (int n = 0; n < 4; n++)
                    #pragma unroll
                    for (int c = 0; c < 4; c++) ac[n][c] = 0.0f;
                #pragma unroll
                for (int jd = 0; jd < 3; jd++) {
                    unsigned a0[4], bq[4];
                    ldsm4(a0, krB + (uint32_t)(rowX * RP + jd * 16 + aSel) * 2);
                    ldsm4(bq, qsB + (uint32_t)(qc * RP + jd * 16 + bSel) * 2);
                    mma_f16(ac[0], a0, bq);
                    mma_f16(ac[1], a0, bq + 2);
                    ldsm4(bq, qsB + (uint32_t)((qc + 16) * RP + jd * 16 + bSel) * 2);
                    mma_f16(ac[2], a0, bq);
                    mma_f16(ac[3], a0, bq + 2);
                }

                const int kg0 = rowX + g, kg1 = kg0 + 8;
                const bool nomask = (rowX + 15 <= qbase) && (rowX + 15 < vlen);
                if (nomask) {
                    #pragma unroll
                    for (int n = 0; n < 4; n++) {
                        const float e0 = fex2(ac[n][0] * C2E);
                        const float e1 = fex2(ac[n][1] * C2E);
                        const float e2 = fex2(ac[n][2] * C2E);
                        const float e3 = fex2(ac[n][3] * C2E);
                        csum[n][0] += e0 + e2;
                        csum[n][1] += e1 + e3;
                        aaP[mt][n >> 1][(n & 1) * 2 + 0] = packh(e0, e1);
                        aaP[mt][n >> 1][(n & 1) * 2 + 1] = packh(e2, e3);
                    }
                } else {
                    const float v0 = (kg0 >= vlen) ? NEG2 : 0.0f;
                    const float v1 = (kg1 >= vlen) ? NEG2 : 0.0f;
                    #pragma unroll
                    for (int n = 0; n < 4; n++) {
                        const int q0 = qbase + n * 8 + tig * 2;
                        float s0 = ac[n][0] * C2E - v0;
                        float s1 = ac[n][1] * C2E - v0;
                        float s2 = ac[n][2] * C2E - v1;
                        float s3 = ac[n][3] * C2E - v1;
                        if (kg0 > q0)     s0 -= NEG2;
                        if (kg0 > q0 + 1) s1 -= NEG2;
                        if (kg1 > q0)     s2 -= NEG2;
                        if (kg1 > q0 + 1) s3 -= NEG2;
                        const float e0 = fex2(s0 + bias2), e1 = fex2(s1 + bias2);
                        const float e2 = fex2(s2 + bias2), e3 = fex2(s3 + bias2);
                        csum[n][0] += e0 + e2;
                        csum[n][1] += e1 + e3;
                        aaP[mt][n >> 1][(n & 1) * 2 + 0] = packh(e0, e1);
                        aaP[mt][n >> 1][(n & 1) * 2 + 1] = packh(e2, e3);
                    }
                }
            }

            // ---- block column-sum -> 1/l ----
            #pragma unroll
            for (int n = 0; n < 4; n++)
                #pragma unroll
                for (int p = 0; p < 2; p++) {
                    float v = csum[n][p];
                    v += __shfl_xor_sync(0xffffffffu, v, 4);
                    v += __shfl_xor_sync(0xffffffffu, v, 8);
                    v += __shfl_xor_sync(0xffffffffu, v, 16);
                    csum[n][p] = v;
                }
            if (g == 0) {
                #pragma unroll
                for (int n = 0; n < 4; n++)
                    *(float2*)&sSum[w * 32 + n * 8 + tig * 2] =
                        make_float2(csum[n][0], csum[n][1]);
            }
            __syncthreads();
            if (t < 32) {
                float l = 0.0f;
                #pragma unroll
                for (int w2 = 0; w2 < 16; w2++) l += sSum[w2 * 32 + t];
                lSc[t] = 1.0f / l;
            }
            __syncthreads();

            // ---- O-mma (scale via half2 multiply) ----
            if (liveA || liveB) {
                #pragma unroll
                for (int kc = 0; kc < 2; kc++) {
                    const float2 rrA = *(const float2*)&lSc[kc * 16 + tig * 2];
                    const float2 rrB = *(const float2*)&lSc[kc * 16 + 8 + tig * 2];
                    const unsigned hA = packh(rrA.x, rrA.y);
                    const unsigned hB = packh(rrB.x, rrB.y);
                    #pragma unroll
                    for (int dd = 0; dd < 3; dd++) {
                        unsigned b4[4];
                        ldsm4t(b4, vsB + (uint32_t)((qc + kc * 16) * RP + dd * 16 + tSel) * 2);
                        #pragma unroll
                        for (int mt = 0; mt < 2; mt++) {
                            if (mt == 0 ? !liveA : !liveB) continue;
                            unsigned aa[4];
                            aa[0] = hmul2u(aaP[mt][kc][0], hA);
                            aa[1] = hmul2u(aaP[mt][kc][1], hA);
                            aa[2] = hmul2u(aaP[mt][kc][2], hB);
                            aa[3] = hmul2u(aaP[mt][kc][3], hB);
                            mma_f16(oacc[mt][dd * 2 + 0], aa, b4);
                            mma_f16(oacc[mt][dd * 2 + 1], aa, b4 + 2);
                        }
                    }
                }
            }
        }
    }

    #pragma unroll
    for (int mt = 0; mt < 2; mt++) {
        const int kg0 = (mt == 0 ? rowA : rowB) + g, kg1 = kg0 + 8;
        const float f0 = (kg0 < qlen) ? 1.0f : 0.0f;
        const float f1 = (kg1 < qlen) ? 1.0f : 0.0f;
        #pragma unroll
        for (int nd = 0; nd < 6; nd++) {
            const int col = h * DHH + nd * 8 + tig * 2;
            *(float2*)(Out + (size_t)(b * LL + kg0) * DOUTC + col) =
                make_float2(oacc[mt][nd][0] * f0, oacc[mt][nd][1] * f0);
            *(float2*)(Out + (size_t)(b * LL + kg1) * DOUTC + col) =
                make_float2(oacc[mt][nd][2] * f1, oacc[mt][nd][3] * f1);
        }
    }
}

// ---------------------------------------------------------------------------
extern "C" void kernel_launch(void* const* d_in, const int* in_sizes, int n_in,
                              void* d_out, int out_size) {
    const float* Qseq = (const float*)d_in[0];
    const float* Kseq = (const float*)d_in[1];
    const float* Vseq = (const float*)d_in[2];
    const float* WQ   = (const float*)d_in[3];
    const float* WK   = (const float*)d_in[4];
    const float* WV   = (const float*)d_in[5];
    const int*   Qlen = (const int*)d_in[6];
    const int*   Vlen = (const int*)d_in[7];

    __half *x16, *w16, *p16;
    cudaGetSymbolAddress((void**)&x16, g_x16);
    cudaGetSymbolAddress((void**)&w16, g_w16);
    cudaGetSymbolAddress((void**)&p16, g_p16);

    cudaFuncSetAttribute(attn_fused, cudaFuncAttributeMaxDynamicSharedMemorySize, SMEM_ATT);

    conv6<<<dim3(1024, 6), 256>>>(Qseq, Kseq, Vseq, WQ, WK, WV);

    proj16<<<dim3(6, 128, 3), 256>>>(x16, w16, p16);

    attn_fused<<<BB * HH, 512, SMEM_ATT>>>(p16, Qlen, Vlen, (float*)d_out);
}

// round 16
// speedup vs baseline: 1.2919x; 1.1206x over previous
#include <cuda_runtime.h>
#include <cuda_fp16.h>
#include <cstdint>

#define BB 32
#define LL 512
#define DIN 768
#define HH 16
#define DHH 48
#define DOUTC 768
#define M_TOT (BB*LL)
#define NEGC 1e12f
#define SCALEC 0.14433756729740643f     /* 1/sqrt(48) */
#define C2E 0.20823031078486745f        /* SCALEC * log2(e) */
#define NEG2 1.4426950408889634e12f     /* NEGC * log2(e) */

// fp16 scratch (static device globals)
__device__ __half g_x16[3][(size_t)M_TOT * DIN];
__device__ __half g_w16[3][(size_t)DIN * DOUTC];
__device__ __half g_p16[3][(size_t)M_TOT * DOUTC];

__device__ __forceinline__ unsigned packh(float lo, float hi) {
    __half2 h = __floats2half2_rn(lo, hi);
    return *(unsigned*)&h;
}
__device__ __forceinline__ unsigned hmul2u(unsigned a, unsigned b) {
    __half2 r = __hmul2(*(__half2*)&a, *(__half2*)&b);
    return *(unsigned*)&r;
}
__device__ __forceinline__ float fex2(float x) {
    float r;
    asm("ex2.approx.f32 %0, %1;" : "=f"(r) : "f"(x));
    return r;
}

__device__ __forceinline__ void mma_f16(float* c, const unsigned* a, const unsigned* b) {
    asm volatile(
        "mma.sync.aligned.m16n8k16.row.col.f32.f16.f16.f32 "
        "{%0,%1,%2,%3}, {%4,%5,%6,%7}, {%8,%9}, {%0,%1,%2,%3};"
        : "+f"(c[0]), "+f"(c[1]), "+f"(c[2]), "+f"(c[3])
        : "r"(a[0]), "r"(a[1]), "r"(a[2]), "r"(a[3]), "r"(b[0]), "r"(b[1]));
}

__device__ __forceinline__ void ldsm4(unsigned* r, uint32_t a) {
    asm volatile("ldmatrix.sync.aligned.m8n8.x4.shared.b16 {%0,%1,%2,%3}, [%4];"
        : "=r"(r[0]), "=r"(r[1]), "=r"(r[2]), "=r"(r[3]) : "r"(a));
}
__device__ __forceinline__ void ldsm4t(unsigned* r, uint32_t a) {
    asm volatile("ldmatrix.sync.aligned.m8n8.x4.trans.shared.b16 {%0,%1,%2,%3}, [%4];"
        : "=r"(r[0]), "=r"(r[1]), "=r"(r[2]), "=r"(r[3]) : "r"(a));
}

__device__ __forceinline__ uint32_t smem_u32(const void* p) {
    uint32_t a;
    asm("{ .reg .u64 t; cvta.to.shared.u64 t, %1; cvt.u32.u64 %0, t; }"
        : "=r"(a) : "l"(p));
    return a;
}

__device__ __forceinline__ void cp16(uint32_t dst, const void* src) {
    asm volatile("cp.async.ca.shared.global [%0], [%1], 16;"
                 :: "r"(dst), "l"(src) : "memory");
}
__device__ __forceinline__ void cp_commit() {
    asm volatile("cp.async.commit_group;" ::: "memory");
}
__device__ __forceinline__ void cp_wait0() {
    asm volatile("cp.async.wait_group 0;" ::: "memory");
}

// ---------------------------------------------------------------------------
// Prep: f32 -> f16, all six tensors in ONE launch (blockIdx.y selects).
// ---------------------------------------------------------------------------
__global__ void conv6(const float* __restrict__ s0, const float* __restrict__ s1,
                      const float* __restrict__ s2, const float* __restrict__ s3,
                      const float* __restrict__ s4, const float* __restrict__ s5) {
    const int y = blockIdx.y;
    const float* s;
    __half* d;
    int n4;
    if (y < 3) {
        s = (y == 0) ? s0 : (y == 1) ? s1 : s2;
        d = g_x16[y];
        n4 = M_TOT * DIN / 4;
    } else {
        s = (y == 3) ? s3 : (y == 4) ? s4 : s5;
        d = g_w16[y - 3];
        n4 = DIN * DOUTC / 4;
    }
    for (int i = blockIdx.x * blockDim.x + threadIdx.x; i < n4;
         i += gridDim.x * blockDim.x) {
        float4 v = ((const float4*)s)[i];
        uint2 o = make_uint2(packh(v.x, v.y), packh(v.z, v.w));
        ((uint2*)d)[i] = o;
    }
}

// ---------------------------------------------------------------------------
// Kernel 1: FP16 proj GEMM, ldmatrix + cp.async.
// R16: K-projection (z==1) blocks whose 128 rows are all >= V_len[b] are
// skipped entirely — their outputs are never consumed by any live MMA tile.
// ---------------------------------------------------------------------------
#define PA 40
#define PB 136
#define NCHUNK (DIN / 32)
__global__ __launch_bounds__(256, 2) void proj16(
    const __half* __restrict__ Xall, const __half* __restrict__ Wall,
    __half* __restrict__ Yall, const int* __restrict__ Vlen) {
    // K skip: rows covered = [mBase, mBase+128), all within batch b = y>>2
    if (blockIdx.z == 1) {
        const int vl = Vlen[blockIdx.y >> 2];
        if (vl > 0 && ((int)(blockIdx.y & 3) * 128) >= vl) return;
    }
    const __half* X = Xall + (size_t)blockIdx.z * M_TOT * DIN;
    const __half* W = Wall + (size_t)blockIdx.z * DIN * DOUTC;
    __half* Y       = Yall + (size_t)blockIdx.z * M_TOT * DOUTC;

    __shared__ __align__(16) __half As[2][128 * PA];
    __shared__ __align__(16) __half Bs[2][32 * PB];

    const int t = threadIdx.x, lane = t & 31, w = t >> 5;
    const int g = lane >> 2, tig = lane & 3;
    const int m0 = (w >> 2) * 64, n0 = (w & 3) * 32;
    const int mBase = blockIdx.y * 128, nBase = blockIdx.x * 128;

    const int arow = t >> 1, ah = t & 1;
    const int brow = t >> 3, bn = (t & 7) * 16;
    const __half* Xp = X + (size_t)(mBase + arow) * DIN + ah * 16;
    const __half* Wp = W + (size_t)brow * DOUTC + nBase + bn;

    const uint32_t aBase = smem_u32(As);
    const uint32_t bBase = smem_u32(Bs);
    const uint32_t aDst = aBase + (uint32_t)(arow * PA + ah * 16) * 2;
    const uint32_t bDst = bBase + (uint32_t)(brow * PB + bn) * 2;
    const int aLO = (lane & 15) * PA + (lane >> 4) * 8;
    const int bLO = ((lane & 7) + ((lane >> 3) & 1) * 8) * PB + (lane >> 4) * 8;

    float acc[4][4][4];
    #pragma unroll
    for (int i = 0; i < 4; i++)
        #pragma unroll
        for (int j = 0; j < 4; j++)
            #pragma unroll
            for (int c = 0; c < 4; c++) acc[i][j][c] = 0.0f;

    cp16(aDst, Xp);
    cp16(aDst + 16, Xp + 8);
    cp16(bDst, Wp);
    cp16(bDst + 16, Wp + 8);
    cp_commit();
    cp_wait0();
    __syncthreads();

    for (int c = 0; c < NCHUNK; c++) {
        const int cur = c & 1;
        const bool more = (c + 1 < NCHUNK);
        if (more) {
            const int kk = (c + 1) * 32;
            const int nxt = cur ^ 1;
            const uint32_t aD2 = aBase + (uint32_t)(nxt * 128 * PA + arow * PA + ah * 16) * 2;
            const uint32_t bD2 = bBase + (uint32_t)(nxt * 32 * PB + brow * PB + bn) * 2;
            cp16(aD2, Xp + kk);
            cp16(aD2 + 16, Xp + kk + 8);
            cp16(bD2, Wp + (size_t)kk * DOUTC);
            cp16(bD2 + 16, Wp + (size_t)kk * DOUTC + 8);
            cp_commit();
        }

        const uint32_t aB = aBase + cur * (128 * PA * 2);
        const uint32_t bB = bBase + cur * (32 * PB * 2);
        #pragma unroll
        for (int ks = 0; ks < 2; ks++) {
            const int k0 = ks * 16;
            unsigned a[4][4];
            #pragma unroll
            for (int i = 0; i < 4; i++)
                ldsm4(a[i], aB + (uint32_t)(((m0 + i * 16) * PA) + k0 + aLO) * 2);
            #pragma unroll
            for (int jp = 0; jp < 2; jp++) {
                unsigned b4[4];
                ldsm4t(b4, bB + (uint32_t)((k0 * PB) + n0 + jp * 16 + bLO) * 2);
                #pragma unroll
                for (int i = 0; i < 4; i++) {
                    mma_f16(acc[i][jp * 2 + 0], a[i], b4);
                    mma_f16(acc[i][jp * 2 + 1], a[i], b4 + 2);
                }
            }
        }

        if (more) cp_wait0();
        __syncthreads();
    }

    #pragma unroll
    for (int i = 0; i < 4; i++) {
        const size_t r1 = (size_t)(mBase + m0 + i * 16 + g);
        const size_t r2 = r1 + 8;
        #pragma unroll
        for (int j = 0; j < 4; j++) {
            const int col = nBase + n0 + j * 8 + tig * 2;
            *(__half2*)(Y + r1 * DOUTC + col) = __floats2half2_rn(acc[i][j][0], acc[i][j][1]);
            *(__half2*)(Y + r2 * DOUTC + col) = __floats2half2_rn(acc[i][j][2], acc[i][j][3]);
        }
    }
}

// ---------------------------------------------------------------------------
// Kernel 2: fused attention R16: R15 + vlen tile liveness cut.
// Tile live <=> rowX <= qbase+31 (causal)  AND  rowX < vlen (key-length).
// vlen==0 special case: liveness reverts to causal-only (bias trick handles
// the reference's all-masked softmax exactly, as since R4).
// ---------------------------------------------------------------------------
#define RP 56
#define OFF_QS   57344
#define OFF_VS   64512
#define OFF_SSUM 71680
#define OFF_LS   73728
#define SMEM_ATT 73984

__global__ __launch_bounds__(512, 1) void attn_fused(
    const __half* __restrict__ P16,
    const int* __restrict__ Qlen, const int* __restrict__ Vlen,
    float* __restrict__ Out) {
    extern __shared__ char smem[];
    __half* KrH = (__half*)smem;
    __half* QsH = (__half*)(smem + OFF_QS);
    __half* VsH = (__half*)(smem + OFF_VS);
    float*  sSum = (float*)(smem + OFF_SSUM);   // [16 warps][32 q]
    float*  lSc  = (float*)(smem + OFF_LS);     // [32]
    const uint32_t krB = smem_u32(smem);
    const uint32_t qsB = krB + OFF_QS;
    const uint32_t vsB = krB + OFF_VS;

    const int b = blockIdx.x >> 4, h = blockIdx.x & 15;
    const int t = threadIdx.x, lane = t & 31, w = t >> 5;
    const int g = lane >> 2, tig = lane & 3;
    const int rowA = w * 16;
    const int rowB = 496 - w * 16;
    const int vlen = Vlen[b], qlen = Qlen[b];
    const int vliv = (vlen == 0) ? LL : vlen;   // liveness cut (vlen==0 -> causal only)
    const float bias2 = (vlen == 0) ? NEG2 : 0.0f;
    const bool okA = (rowA < vliv), okB = (rowB < vliv);

    const int aSel = (lane & 15) * RP + (lane >> 4) * 8;
    const int bSel = ((lane & 7) + ((lane >> 4) << 3)) * RP + ((lane >> 3) & 1) * 8;
    const int tSel = ((lane & 7) + (((lane >> 3) & 1) << 3)) * RP + (lane >> 4) * 8;

    const __half* qsrc = P16 + (size_t)(b * LL) * DOUTC + h * DHH;
    const __half* ksrc = qsrc + (size_t)M_TOT * DOUTC;
    const __half* vsrc = ksrc + (size_t)M_TOT * DOUTC;

    for (int i = t; i < 3072; i += 512) {
        const int row = i / 6, c4 = i % 6;
        *(uint4*)(KrH + row * RP + c4 * 8) =
            *(const uint4*)(ksrc + (size_t)row * DOUTC + c4 * 8);
    }

    const int arr0 = t >= 384;
    const int j0 = arr0 ? t - 384 : t;
    const int row0 = j0 / 6, c40 = j0 % 6;
    const __half* src0 = (arr0 ? vsrc : qsrc) + (size_t)row0 * DOUTC + c40 * 8;
    __half* dst0 = (arr0 ? VsH : QsH) + row0 * RP + c40 * 8;
    const int j1 = t + 128;
    const int row1 = j1 / 6, c41 = j1 % 6;
    const __half* src1 = vsrc + (size_t)row1 * DOUTC + c41 * 8;
    __half* dst1 = VsH + row1 * RP + c41 * 8;

    float oacc[2][6][4];
    #pragma unroll
    for (int mt = 0; mt < 2; mt++)
        #pragma unroll
        for (int nd = 0; nd < 6; nd++)
            #pragma unroll
            for (int c = 0; c < 4; c++) oacc[mt][nd][c] = 0.0f;

    for (int qt = 0; qt < 8; qt++) {
        const size_t qoff = (size_t)(qt * 64) * DOUTC;
        uint4 p0 = *(const uint4*)(src0 + qoff);
        uint4 p1;
        if (t < 256) p1 = *(const uint4*)(src1 + qoff);
        __syncthreads();
        *(uint4*)dst0 = p0;
        if (t < 256) *(uint4*)dst1 = p1;
        __syncthreads();

        #pragma unroll
        for (int sub = 0; sub < 2; sub++) {
            const int qc = sub * 32;
            const int qbase = qt * 64 + qc;
            const bool liveA = okA && (rowA <= qbase + 31);
            const bool liveB = okB && (rowB <= qbase + 31);

            float csum[4][2];
            #pragma unroll
            for (int n = 0; n < 4; n++) { csum[n][0] = 0.0f; csum[n][1] = 0.0f; }

            unsigned aaP[2][2][4];   // [mt][kc][frag] packed exp (unscaled)

            // ---- sequential per-mt S + exp + pack (low register peak) ----
            #pragma unroll
            for (int mt = 0; mt < 2; mt++) {
                const bool liveX = (mt == 0) ? liveA : liveB;
                if (!liveX) continue;
                const int rowX = (mt == 0) ? rowA : rowB;

                float ac[4][4];
                #pragma unroll
                for (int n = 0; n < 4; n++)
                    #pragma unroll
                    for (int c = 0; c < 4; c++) ac[n][c] = 0.0f;
                #pragma unroll
                for (int jd = 0; jd < 3; jd++) {
                    unsigned a0[4], bq[4];
                    ldsm4(a0, krB + (uint32_t)(rowX * RP + jd * 16 + aSel) * 2);
                    ldsm4(bq, qsB + (uint32_t)(qc * RP + jd * 16 + bSel) * 2);
                    mma_f16(ac[0], a0, bq);
                    mma_f16(ac[1], a0, bq + 2);
                    ldsm4(bq, qsB + (uint32_t)((qc + 16) * RP + jd * 16 + bSel) * 2);
                    mma_f16(ac[2], a0, bq);
                    mma_f16(ac[3], a0, bq + 2);
                }

                const int kg0 = rowX + g, kg1 = kg0 + 8;
                const bool nomask = (rowX + 15 <= qbase) && (rowX + 15 < vlen);
                if (nomask) {
                    #pragma unroll
                    for (int n = 0; n < 4; n++) {
                        const float e0 = fex2(ac[n][0] * C2E);
                        const float e1 = fex2(ac[n][1] * C2E);
                        const float e2 = fex2(ac[n][2] * C2E);
                        const float e3 = fex2(ac[n][3] * C2E);
                        csum[n][0] += e0 + e2;
                        csum[n][1] += e1 + e3;
                        aaP[mt][n >> 1][(n & 1) * 2 + 0] = packh(e0, e1);
                        aaP[mt][n >> 1][(n & 1) * 2 + 1] = packh(e2, e3);
                    }
                } else {
                    const float v0 = (kg0 >= vlen) ? NEG2 : 0.0f;
                    const float v1 = (kg1 >= vlen) ? NEG2 : 0.0f;
                    #pragma unroll
                    for (int n = 0; n < 4; n++) {
                        const int q0 = qbase + n * 8 + tig * 2;
                        float s0 = ac[n][0] * C2E - v0;
                        float s1 = ac[n][1] * C2E - v0;
                        float s2 = ac[n][2] * C2E - v1;
                        float s3 = ac[n][3] * C2E - v1;
                        if (kg0 > q0)     s0 -= NEG2;
                        if (kg0 > q0 + 1) s1 -= NEG2;
                        if (kg1 > q0)     s2 -= NEG2;
                        if (kg1 > q0 + 1) s3 -= NEG2;
                        const float e0 = fex2(s0 + bias2), e1 = fex2(s1 + bias2);
                        const float e2 = fex2(s2 + bias2), e3 = fex2(s3 + bias2);
                        csum[n][0] += e0 + e2;
                        csum[n][1] += e1 + e3;
                        aaP[mt][n >> 1][(n & 1) * 2 + 0] = packh(e0, e1);
                        aaP[mt][n >> 1][(n & 1) * 2 + 1] = packh(e2, e3);
                    }
                }
            }

            // ---- block column-sum -> 1/l ----
            #pragma unroll
            for (int n = 0; n < 4; n++)
                #pragma unroll
                for (int p = 0; p < 2; p++) {
                    float v = csum[n][p];
                    v += __shfl_xor_sync(0xffffffffu, v, 4);
                    v += __shfl_xor_sync(0xffffffffu, v, 8);
                    v += __shfl_xor_sync(0xffffffffu, v, 16);
                    csum[n][p] = v;
                }
            if (g == 0) {
                #pragma unroll
                for (int n = 0; n < 4; n++)
                    *(float2*)&sSum[w * 32 + n * 8 + tig * 2] =
                        make_float2(csum[n][0], csum[n][1]);
            }
            __syncthreads();
            if (t < 32) {
                float l = 0.0f;
                #pragma unroll
                for (int w2 = 0; w2 < 16; w2++) l += sSum[w2 * 32 + t];
                lSc[t] = 1.0f / l;
            }
            __syncthreads();

            // ---- O-mma (scale via half2 multiply) ----
            if (liveA || liveB) {
                #pragma unroll
                for (int kc = 0; kc < 2; kc++) {
                    const float2 rrA = *(const float2*)&lSc[kc * 16 + tig * 2];
                    const float2 rrB = *(const float2*)&lSc[kc * 16 + 8 + tig * 2];
                    const unsigned hA = packh(rrA.x, rrA.y);
                    const unsigned hB = packh(rrB.x, rrB.y);
                    #pragma unroll
                    for (int dd = 0; dd < 3; dd++) {
                        unsigned b4[4];
                        ldsm4t(b4, vsB + (uint32_t)((qc + kc * 16) * RP + dd * 16 + tSel) * 2);
                        #pragma unroll
                        for (int mt = 0; mt < 2; mt++) {
                            if (mt == 0 ? !liveA : !liveB) continue;
                            unsigned aa[4];
                            aa[0] = hmul2u(aaP[mt][kc][0], hA);
                            aa[1] = hmul2u(aaP[mt][kc][1], hA);
                            aa[2] = hmul2u(aaP[mt][kc][2], hB);
                            aa[3] = hmul2u(aaP[mt][kc][3], hB);
                            mma_f16(oacc[mt][dd * 2 + 0], aa, b4);
                            mma_f16(oacc[mt][dd * 2 + 1], aa, b4 + 2);
                        }
                    }
                }
            }
        }
    }

    #pragma unroll
    for (int mt = 0; mt < 2; mt++) {
        const int kg0 = (mt == 0 ? rowA : rowB) + g, kg1 = kg0 + 8;
        const float f0 = (kg0 < qlen) ? 1.0f : 0.0f;
        const float f1 = (kg1 < qlen) ? 1.0f : 0.0f;
        #pragma unroll
        for (int nd = 0; nd < 6; nd++) {
            const int col = h * DHH + nd * 8 + tig * 2;
            *(float2*)(Out + (size_t)(b * LL + kg0) * DOUTC + col) =
                make_float2(oacc[mt][nd][0] * f0, oacc[mt][nd][1] * f0);
            *(float2*)(Out + (size_t)(b * LL + kg1) * DOUTC + col) =
                make_float2(oacc[mt][nd][2] * f1, oacc[mt][nd][3] * f1);
        }
    }
}

// ---------------------------------------------------------------------------
extern "C" void kernel_launch(void* const* d_in, const int* in_sizes, int n_in,
                              void* d_out, int out_size) {
    const float* Qseq = (const float*)d_in[0];
    const float* Kseq = (const float*)d_in[1];
    const float* Vseq = (const float*)d_in[2];
    const float* WQ   = (const float*)d_in[3];
    const float* WK   = (const float*)d_in[4];
    const float* WV   = (const float*)d_in[5];
    const int*   Qlen = (const int*)d_in[6];
    const int*   Vlen = (const int*)d_in[7];

    __half *x16, *w16, *p16;
    cudaGetSymbolAddress((void**)&x16, g_x16);
    cudaGetSymbolAddress((void**)&w16, g_w16);
    cudaGetSymbolAddress((void**)&p16, g_p16);

    cudaFuncSetAttribute(attn_fused, cudaFuncAttributeMaxDynamicSharedMemorySize, SMEM_ATT);

    conv6<<<dim3(1024, 6), 256>>>(Qseq, Kseq, Vseq, WQ, WK, WV);

    proj16<<<dim3(6, 128, 3), 256>>>(x16, w16, p16, Vlen);

    attn_fused<<<BB * HH, 512, SMEM_ATT>>>(p16, Qlen, Vlen, (float*)d_out);
}

// round 17
// speedup vs baseline: 1.3176x; 1.0199x over previous
#include <cuda_runtime.h>
#include <cuda_fp16.h>
#include <cstdint>

#define BB 32
#define LL 512
#define DIN 768
#define HH 16
#define DHH 48
#define DOUTC 768
#define M_TOT (BB*LL)
#define NEGC 1e12f
#define SCALEC 0.14433756729740643f     /* 1/sqrt(48) */
#define C2E 0.20823031078486745f        /* SCALEC * log2(e) */
#define NEG2 1.4426950408889634e12f     /* NEGC * log2(e) */

// fp16 scratch (static device globals)
__device__ __half g_x16[3][(size_t)M_TOT * DIN];
__device__ __half g_w16[3][(size_t)DIN * DOUTC];
__device__ __half g_p16[3][(size_t)M_TOT * DOUTC];

__device__ __forceinline__ unsigned packh(float lo, float hi) {
    __half2 h = __floats2half2_rn(lo, hi);
    return *(unsigned*)&h;
}
__device__ __forceinline__ unsigned hmul2u(unsigned a, unsigned b) {
    __half2 r = __hmul2(*(__half2*)&a, *(__half2*)&b);
    return *(unsigned*)&r;
}
__device__ __forceinline__ float fex2(float x) {
    float r;
    asm("ex2.approx.f32 %0, %1;" : "=f"(r) : "f"(x));
    return r;
}

__device__ __forceinline__ void mma_f16(float* c, const unsigned* a, const unsigned* b) {
    asm volatile(
        "mma.sync.aligned.m16n8k16.row.col.f32.f16.f16.f32 "
        "{%0,%1,%2,%3}, {%4,%5,%6,%7}, {%8,%9}, {%0,%1,%2,%3};"
        : "+f"(c[0]), "+f"(c[1]), "+f"(c[2]), "+f"(c[3])
        : "r"(a[0]), "r"(a[1]), "r"(a[2]), "r"(a[3]), "r"(b[0]), "r"(b[1]));
}

__device__ __forceinline__ void ldsm4(unsigned* r, uint32_t a) {
    asm volatile("ldmatrix.sync.aligned.m8n8.x4.shared.b16 {%0,%1,%2,%3}, [%4];"
        : "=r"(r[0]), "=r"(r[1]), "=r"(r[2]), "=r"(r[3]) : "r"(a));
}
__device__ __forceinline__ void ldsm4t(unsigned* r, uint32_t a) {
    asm volatile("ldmatrix.sync.aligned.m8n8.x4.trans.shared.b16 {%0,%1,%2,%3}, [%4];"
        : "=r"(r[0]), "=r"(r[1]), "=r"(r[2]), "=r"(r[3]) : "r"(a));
}

__device__ __forceinline__ uint32_t smem_u32(const void* p) {
    uint32_t a;
    asm("{ .reg .u64 t; cvta.to.shared.u64 t, %1; cvt.u32.u64 %0, t; }"
        : "=r"(a) : "l"(p));
    return a;
}

__device__ __forceinline__ void cp16(uint32_t dst, const void* src) {
    asm volatile("cp.async.ca.shared.global [%0], [%1], 16;"
                 :: "r"(dst), "l"(src) : "memory");
}
__device__ __forceinline__ void cp_commit() {
    asm volatile("cp.async.commit_group;" ::: "memory");
}
__device__ __forceinline__ void cp_wait0() {
    asm volatile("cp.async.wait_group 0;" ::: "memory");
}

// ---------------------------------------------------------------------------
// Prep: f32 -> f16, all six tensors in ONE launch (blockIdx.y selects).
// R17: K conversion (y==1) skips rows >= V_len[b] — never consumed downstream.
// ---------------------------------------------------------------------------
__global__ void conv6(const float* __restrict__ s0, const float* __restrict__ s1,
                      const float* __restrict__ s2, const float* __restrict__ s3,
                      const float* __restrict__ s4, const float* __restrict__ s5,
                      const int* __restrict__ Vlen) {
    const int y = blockIdx.y;
    const float* s;
    __half* d;
    int n4;
    if (y < 3) {
        s = (y == 0) ? s0 : (y == 1) ? s1 : s2;
        d = g_x16[y];
        n4 = M_TOT * DIN / 4;
    } else {
        s = (y == 3) ? s3 : (y == 4) ? s4 : s5;
        d = g_w16[y - 3];
        n4 = DIN * DOUTC / 4;
    }
    const bool isK = (y == 1);
    for (int i = blockIdx.x * blockDim.x + threadIdx.x; i < n4;
         i += gridDim.x * blockDim.x) {
        if (isK) {
            const int row = i / (DIN / 4);           // global seq row
            const int vl = Vlen[row >> 9];           // row / 512
            if (vl > 0 && (row & 511) >= vl) continue;
        }
        float4 v = ((const float4*)s)[i];
        uint2 o = make_uint2(packh(v.x, v.y), packh(v.z, v.w));
        ((uint2*)d)[i] = o;
    }
}

// ---------------------------------------------------------------------------
// Kernel 1: FP16 proj GEMM, ldmatrix + cp.async.
// K-projection (z==1) blocks fully >= V_len[b] skipped (validated R16).
// ---------------------------------------------------------------------------
#define PA 40
#define PB 136
#define NCHUNK (DIN / 32)
__global__ __launch_bounds__(256, 2) void proj16(
    const __half* __restrict__ Xall, const __half* __restrict__ Wall,
    __half* __restrict__ Yall, const int* __restrict__ Vlen) {
    if (blockIdx.z == 1) {
        const int vl = Vlen[blockIdx.y >> 2];
        if (vl > 0 && ((int)(blockIdx.y & 3) * 128) >= vl) return;
    }
    const __half* X = Xall + (size_t)blockIdx.z * M_TOT * DIN;
    const __half* W = Wall + (size_t)blockIdx.z * DIN * DOUTC;
    __half* Y       = Yall + (size_t)blockIdx.z * M_TOT * DOUTC;

    __shared__ __align__(16) __half As[2][128 * PA];
    __shared__ __align__(16) __half Bs[2][32 * PB];

    const int t = threadIdx.x, lane = t & 31, w = t >> 5;
    const int g = lane >> 2, tig = lane & 3;
    const int m0 = (w >> 2) * 64, n0 = (w & 3) * 32;
    const int mBase = blockIdx.y * 128, nBase = blockIdx.x * 128;

    const int arow = t >> 1, ah = t & 1;
    const int brow = t >> 3, bn = (t & 7) * 16;
    const __half* Xp = X + (size_t)(mBase + arow) * DIN + ah * 16;
    const __half* Wp = W + (size_t)brow * DOUTC + nBase + bn;

    const uint32_t aBase = smem_u32(As);
    const uint32_t bBase = smem_u32(Bs);
    const uint32_t aDst = aBase + (uint32_t)(arow * PA + ah * 16) * 2;
    const uint32_t bDst = bBase + (uint32_t)(brow * PB + bn) * 2;
    const int aLO = (lane & 15) * PA + (lane >> 4) * 8;
    const int bLO = ((lane & 7) + ((lane >> 3) & 1) * 8) * PB + (lane >> 4) * 8;

    float acc[4][4][4];
    #pragma unroll
    for (int i = 0; i < 4; i++)
        #pragma unroll
        for (int j = 0; j < 4; j++)
            #pragma unroll
            for (int c = 0; c < 4; c++) acc[i][j][c] = 0.0f;

    cp16(aDst, Xp);
    cp16(aDst + 16, Xp + 8);
    cp16(bDst, Wp);
    cp16(bDst + 16, Wp + 8);
    cp_commit();
    cp_wait0();
    __syncthreads();

    for (int c = 0; c < NCHUNK; c++) {
        const int cur = c & 1;
        const bool more = (c + 1 < NCHUNK);
        if (more) {
            const int kk = (c + 1) * 32;
            const int nxt = cur ^ 1;
            const uint32_t aD2 = aBase + (uint32_t)(nxt * 128 * PA + arow * PA + ah * 16) * 2;
            const uint32_t bD2 = bBase + (uint32_t)(nxt * 32 * PB + brow * PB + bn) * 2;
            cp16(aD2, Xp + kk);
            cp16(aD2 + 16, Xp + kk + 8);
            cp16(bD2, Wp + (size_t)kk * DOUTC);
            cp16(bD2 + 16, Wp + (size_t)kk * DOUTC + 8);
            cp_commit();
        }

        const uint32_t aB = aBase + cur * (128 * PA * 2);
        const uint32_t bB = bBase + cur * (32 * PB * 2);
        #pragma unroll
        for (int ks = 0; ks < 2; ks++) {
            const int k0 = ks * 16;
            unsigned a[4][4];
            #pragma unroll
            for (int i = 0; i < 4; i++)
                ldsm4(a[i], aB + (uint32_t)(((m0 + i * 16) * PA) + k0 + aLO) * 2);
            #pragma unroll
            for (int jp = 0; jp < 2; jp++) {
                unsigned b4[4];
                ldsm4t(b4, bB + (uint32_t)((k0 * PB) + n0 + jp * 16 + bLO) * 2);
                #pragma unroll
                for (int i = 0; i < 4; i++) {
                    mma_f16(acc[i][jp * 2 + 0], a[i], b4);
                    mma_f16(acc[i][jp * 2 + 1], a[i], b4 + 2);
                }
            }
        }

        if (more) cp_wait0();
        __syncthreads();
    }

    #pragma unroll
    for (int i = 0; i < 4; i++) {
        const size_t r1 = (size_t)(mBase + m0 + i * 16 + g);
        const size_t r2 = r1 + 8;
        #pragma unroll
        for (int j = 0; j < 4; j++) {
            const int col = nBase + n0 + j * 8 + tig * 2;
            *(__half2*)(Y + r1 * DOUTC + col) = __floats2half2_rn(acc[i][j][0], acc[i][j][1]);
            *(__half2*)(Y + r2 * DOUTC + col) = __floats2half2_rn(acc[i][j][2], acc[i][j][3]);
        }
    }
}

// ---------------------------------------------------------------------------
// Kernel 2: fused attention R17: R16 + qlen O-skip.
// S+exp always runs for live tiles (feeds softmax sums); O-mma runs only if
// the tile's output rows survive the Q_len mask (rowX < qlen).
// ---------------------------------------------------------------------------
#define RP 56
#define OFF_QS   57344
#define OFF_VS   64512
#define OFF_SSUM 71680
#define OFF_LS   73728
#define SMEM_ATT 73984

__global__ __launch_bounds__(512, 1) void attn_fused(
    const __half* __restrict__ P16,
    const int* __restrict__ Qlen, const int* __restrict__ Vlen,
    float* __restrict__ Out) {
    extern __shared__ char smem[];
    __half* KrH = (__half*)smem;
    __half* QsH = (__half*)(smem + OFF_QS);
    __half* VsH = (__half*)(smem + OFF_VS);
    float*  sSum = (float*)(smem + OFF_SSUM);   // [16 warps][32 q]
    float*  lSc  = (float*)(smem + OFF_LS);     // [32]
    const uint32_t krB = smem_u32(smem);
    const uint32_t qsB = krB + OFF_QS;
    const uint32_t vsB = krB + OFF_VS;

    const int b = blockIdx.x >> 4, h = blockIdx.x & 15;
    const int t = threadIdx.x, lane = t & 31, w = t >> 5;
    const int g = lane >> 2, tig = lane & 3;
    const int rowA = w * 16;
    const int rowB = 496 - w * 16;
    const int vlen = Vlen[b], qlen = Qlen[b];
    const int vliv = (vlen == 0) ? LL : vlen;
    const float bias2 = (vlen == 0) ? NEG2 : 0.0f;
    const bool okA = (rowA < vliv), okB = (rowB < vliv);
    const bool oA = (rowA < qlen), oB = (rowB < qlen);   // output-row liveness

    const int aSel = (lane & 15) * RP + (lane >> 4) * 8;
    const int bSel = ((lane & 7) + ((lane >> 4) << 3)) * RP + ((lane >> 3) & 1) * 8;
    const int tSel = ((lane & 7) + (((lane >> 3) & 1) << 3)) * RP + (lane >> 4) * 8;

    const __half* qsrc = P16 + (size_t)(b * LL) * DOUTC + h * DHH;
    const __half* ksrc = qsrc + (size_t)M_TOT * DOUTC;
    const __half* vsrc = ksrc + (size_t)M_TOT * DOUTC;

    for (int i = t; i < 3072; i += 512) {
        const int row = i / 6, c4 = i % 6;
        *(uint4*)(KrH + row * RP + c4 * 8) =
            *(const uint4*)(ksrc + (size_t)row * DOUTC + c4 * 8);
    }

    const int arr0 = t >= 384;
    const int j0 = arr0 ? t - 384 : t;
    const int row0 = j0 / 6, c40 = j0 % 6;
    const __half* src0 = (arr0 ? vsrc : qsrc) + (size_t)row0 * DOUTC + c40 * 8;
    __half* dst0 = (arr0 ? VsH : QsH) + row0 * RP + c40 * 8;
    const int j1 = t + 128;
    const int row1 = j1 / 6, c41 = j1 % 6;
    const __half* src1 = vsrc + (size_t)row1 * DOUTC + c41 * 8;
    __half* dst1 = VsH + row1 * RP + c41 * 8;

    float oacc[2][6][4];
    #pragma unroll
    for (int mt = 0; mt < 2; mt++)
        #pragma unroll
        for (int nd = 0; nd < 6; nd++)
            #pragma unroll
            for (int c = 0; c < 4; c++) oacc[mt][nd][c] = 0.0f;

    for (int qt = 0; qt < 8; qt++) {
        const size_t qoff = (size_t)(qt * 64) * DOUTC;
        uint4 p0 = *(const uint4*)(src0 + qoff);
        uint4 p1;
        if (t < 256) p1 = *(const uint4*)(src1 + qoff);
        __syncthreads();
        *(uint4*)dst0 = p0;
        if (t < 256) *(uint4*)dst1 = p1;
        __syncthreads();

        #pragma unroll
        for (int sub = 0; sub < 2; sub++) {
            const int qc = sub * 32;
            const int qbase = qt * 64 + qc;
            const bool liveA = okA && (rowA <= qbase + 31);
            const bool liveB = okB && (rowB <= qbase + 31);

            float csum[4][2];
            #pragma unroll
            for (int n = 0; n < 4; n++) { csum[n][0] = 0.0f; csum[n][1] = 0.0f; }

            unsigned aaP[2][2][4];   // [mt][kc][frag] packed exp (unscaled)

            // ---- sequential per-mt S + exp + pack (low register peak) ----
            #pragma unroll
            for (int mt = 0; mt < 2; mt++) {
                const bool liveX = (mt == 0) ? liveA : liveB;
                if (!liveX) continue;
                const int rowX = (mt == 0) ? rowA : rowB;

                float ac[4][4];
                #pragma unroll
                for (int n = 0; n < 4; n++)
                    #pragma unroll
                    for (int c = 0; c < 4; c++) ac[n][c] = 0.0f;
                #pragma unroll
                for (int jd = 0; jd < 3; jd++) {
                    unsigned a0[4], bq[4];
                    ldsm4(a0, krB + (uint32_t)(rowX * RP + jd * 16 + aSel) * 2);
                    ldsm4(bq, qsB + (uint32_t)(qc * RP + jd * 16 + bSel) * 2);
                    mma_f16(ac[0], a0, bq);
                    mma_f16(ac[1], a0, bq + 2);
                    ldsm4(bq, qsB + (uint32_t)((qc + 16) * RP + jd * 16 + bSel) * 2);
                    mma_f16(ac[2], a0, bq);
                    mma_f16(ac[3], a0, bq + 2);
                }

                const int kg0 = rowX + g, kg1 = kg0 + 8;
                const bool nomask = (rowX + 15 <= qbase) && (rowX + 15 < vlen);
                if (nomask) {
                    #pragma unroll
                    for (int n = 0; n < 4; n++) {
                        const float e0 = fex2(ac[n][0] * C2E);
                        const float e1 = fex2(ac[n][1] * C2E);
                        const float e2 = fex2(ac[n][2] * C2E);
                        const float e3 = fex2(ac[n][3] * C2E);
                        csum[n][0] += e0 + e2;
                        csum[n][1] += e1 + e3;
                        aaP[mt][n >> 1][(n & 1) * 2 + 0] = packh(e0, e1);
                        aaP[mt][n >> 1][(n & 1) * 2 + 1] = packh(e2, e3);
                    }
                } else {
                    const float v0 = (kg0 >= vlen) ? NEG2 : 0.0f;
                    const float v1 = (kg1 >= vlen) ? NEG2 : 0.0f;
                    #pragma unroll
                    for (int n = 0; n < 4; n++) {
                        const int q0 = qbase + n * 8 + tig * 2;
                        float s0 = ac[n][0] * C2E - v0;
                        float s1 = ac[n][1] * C2E - v0;
                        float s2 = ac[n][2] * C2E - v1;
                        float s3 = ac[n][3] * C2E - v1;
                        if (kg0 > q0)     s0 -= NEG2;
                        if (kg0 > q0 + 1) s1 -= NEG2;
                        if (kg1 > q0)     s2 -= NEG2;
                        if (kg1 > q0 + 1) s3 -= NEG2;
                        const float e0 = fex2(s0 + bias2), e1 = fex2(s1 + bias2);
                        const float e2 = fex2(s2 + bias2), e3 = fex2(s3 + bias2);
                        csum[n][0] += e0 + e2;
                        csum[n][1] += e1 + e3;
                        aaP[mt][n >> 1][(n & 1) * 2 + 0] = packh(e0, e1);
                        aaP[mt][n >> 1][(n & 1) * 2 + 1] = packh(e2, e3);
                    }
                }
            }

            // ---- block column-sum -> 1/l ----
            #pragma unroll
            for (int n = 0; n < 4; n++)
                #pragma unroll
                for (int p = 0; p < 2; p++) {
                    float v = csum[n][p];
                    v += __shfl_xor_sync(0xffffffffu, v, 4);
                    v += __shfl_xor_sync(0xffffffffu, v, 8);
                    v += __shfl_xor_sync(0xffffffffu, v, 16);
                    csum[n][p] = v;
                }
            if (g == 0) {
                #pragma unroll
                for (int n = 0; n < 4; n++)
                    *(float2*)&sSum[w * 32 + n * 8 + tig * 2] =
                        make_float2(csum[n][0], csum[n][1]);
            }
            __syncthreads();
            if (t < 32) {
                float l = 0.0f;
                #pragma unroll
                for (int w2 = 0; w2 < 16; w2++) l += sSum[w2 * 32 + t];
                lSc[t] = 1.0f / l;
            }
            __syncthreads();

            // ---- O-mma (only for tiles whose output rows survive Q_len) ----
            const bool outA = liveA && oA;
            const bool outB = liveB && oB;
            if (outA || outB) {
                #pragma unroll
                for (int kc = 0; kc < 2; kc++) {
                    const float2 rrA = *(const float2*)&lSc[kc * 16 + tig * 2];
                    const float2 rrB = *(const float2*)&lSc[kc * 16 + 8 + tig * 2];
                    const unsigned hA = packh(rrA.x, rrA.y);
                    const unsigned hB = packh(rrB.x, rrB.y);
                    #pragma unroll
                    for (int dd = 0; dd < 3; dd++) {
                        unsigned b4[4];
                        ldsm4t(b4, vsB + (uint32_t)((qc + kc * 16) * RP + dd * 16 + tSel) * 2);
                        #pragma unroll
                        for (int mt = 0; mt < 2; mt++) {
                            if (mt == 0 ? !outA : !outB) continue;
                            unsigned aa[4];
                            aa[0] = hmul2u(aaP[mt][kc][0], hA);
                            aa[1] = hmul2u(aaP[mt][kc][1], hA);
                            aa[2] = hmul2u(aaP[mt][kc][2], hB);
                            aa[3] = hmul2u(aaP[mt][kc][3], hB);
                            mma_f16(oacc[mt][dd * 2 + 0], aa, b4);
                            mma_f16(oacc[mt][dd * 2 + 1], aa, b4 + 2);
                        }
                    }
                }
            }
        }
    }

    #pragma unroll
    for (int mt = 0; mt < 2; mt++) {
        const int kg0 = (mt == 0 ? rowA : rowB) + g, kg1 = kg0 + 8;
        const float f0 = (kg0 < qlen) ? 1.0f : 0.0f;
        const float f1 = (kg1 < qlen) ? 1.0f : 0.0f;
        #pragma unroll
        for (int nd = 0; nd < 6; nd++) {
            const int col = h * DHH + nd * 8 + tig * 2;
            *(float2*)(Out + (size_t)(b * LL + kg0) * DOUTC + col) =
                make_float2(oacc[mt][nd][0] * f0, oacc[mt][nd][1] * f0);
            *(float2*)(Out + (size_t)(b * LL + kg1) * DOUTC + col) =
                make_float2(oacc[mt][nd][2] * f1, oacc[mt][nd][3] * f1);
        }
    }
}

// ---------------------------------------------------------------------------
extern "C" void kernel_launch(void* const* d_in, const int* in_sizes, int n_in,
                              void* d_out, int out_size) {
    const float* Qseq = (const float*)d_in[0];
    const float* Kseq = (const float*)d_in[1];
    const float* Vseq = (const float*)d_in[2];
    const float* WQ   = (const float*)d_in[3];
    const float* WK   = (const float*)d_in[4];
    const float* WV   = (const float*)d_in[5];
    const int*   Qlen = (const int*)d_in[6];
    const int*   Vlen = (const int*)d_in[7];

    __half *x16, *w16, *p16;
    cudaGetSymbolAddress((void**)&x16, g_x16);
    cudaGetSymbolAddress((void**)&w16, g_w16);
    cudaGetSymbolAddress((void**)&p16, g_p16);

    cudaFuncSetAttribute(attn_fused, cudaFuncAttributeMaxDynamicSharedMemorySize, SMEM_ATT);

    conv6<<<dim3(1024, 6), 256>>>(Qseq, Kseq, Vseq, WQ, WK, WV, Vlen);

    proj16<<<dim3(6, 128, 3), 256>>>(x16, w16, p16, Vlen);

    attn_fused<<<BB * HH, 512, SMEM_ATT>>>(p16, Qlen, Vlen, (float*)d_out);
}